// round 15
// baseline (speedup 1.0000x reference)
#include <cuda_runtime.h>
#include <cuda_fp16.h>
#include <cstdint>
#include <string.h>
#include <math.h>

#define B_  2
#define L_  1024
#define S_  4096
#define H_  16
#define LD  1024
#define ID  2048
#define R_  256

typedef __half hf;

// ---- scratch (device globals, allocation-free) ----
__device__ hf g_Lx[B_*L_*LD];
__device__ hf g_Xx[B_*S_*ID];
__device__ hf g_WqT[LD*LD], g_WcT[R_*ID], g_WkT[LD*R_], g_WvT[LD*R_], g_WoT[LD*LD];
__device__ hf g_Q[B_*L_*LD];
__device__ hf g_C[B_*S_*R_];
__device__ hf g_K[B_*S_*LD];
__device__ hf g_Vt[B_*LD*S_];
__device__ hf g_P[(size_t)B_*H_*L_*S_];
__device__ hf g_AO[B_*L_*LD];
__device__ float g_part[(size_t)B_*H_*L_*32];
__device__ float g_inv[B_*H_*L_];

// ---- helpers ----
__device__ __forceinline__ uint32_t s2u(const void* p){ uint32_t a; asm("{ .reg .u64 t; cvta.to.shared.u64 t, %1; cvt.u32.u64 %0, t; }":"=r"(a):"l"(p)); return a; }
__device__ __forceinline__ void cp16(uint32_t d, const void* g){ asm volatile("cp.async.cg.shared.global [%0],[%1],16;"::"r"(d),"l"(g)); }
#define CP_COMMIT() asm volatile("cp.async.commit_group;":::"memory")
#define CP_WAIT0()  asm volatile("cp.async.wait_group 0;":::"memory")
__device__ __forceinline__ void ldsm4(uint32_t a, uint32_t* r){
    asm volatile("ldmatrix.sync.aligned.m8n8.x4.shared.b16 {%0,%1,%2,%3},[%4];"
        :"=r"(r[0]),"=r"(r[1]),"=r"(r[2]),"=r"(r[3]):"r"(a));
}
__device__ __forceinline__ void mma16816(float* c, const uint32_t* a, const uint32_t* b){
    asm volatile("mma.sync.aligned.m16n8k16.row.col.f32.f16.f16.f32 "
        "{%0,%1,%2,%3},{%4,%5,%6,%7},{%8,%9},{%0,%1,%2,%3};"
        :"+f"(c[0]),"+f"(c[1]),"+f"(c[2]),"+f"(c[3])
        :"r"(a[0]),"r"(a[1]),"r"(a[2]),"r"(a[3]),"r"(b[0]),"r"(b[1]));
}
__device__ __forceinline__ uint32_t pkh(float a, float b){ __half2 t=__floats2half2_rn(a,b); return *(uint32_t*)&t; }

// ---- fused activation convert: latent + x in one launch ----
__global__ __launch_bounds__(256) void cvtA(const float* __restrict__ lat, const float* __restrict__ x,
                                            hf* __restrict__ Lx, hf* __restrict__ Xx, long nL, long nT){
    for(long i = blockIdx.x*256L + threadIdx.x; i < nT; i += (long)gridDim.x*256){
        const float4 v = (i < nL) ? ((const float4*)lat)[i] : ((const float4*)x)[i - nL];
        uint2 o = make_uint2(pkh(v.x,v.y), pkh(v.z,v.w));
        if(i < nL) ((uint2*)Lx)[i] = o; else ((uint2*)Xx)[i - nL] = o;
    }
}
// ---- fused weight transpose-convert: 5 weights, z-selected ----
struct WT5 { const float* W[5]; hf* T[5]; int K[5], N[5]; };
__global__ __launch_bounds__(256) void cvtW(WT5 w){
    const int wi = blockIdx.z;
    const int K = w.K[wi], N = w.N[wi];
    const int n0 = blockIdx.x*32, k0 = blockIdx.y*32;
    if(n0 >= N || k0 >= K) return;
    __shared__ float t[32][33];
    const float* W = w.W[wi]; hf* T = w.T[wi];
    int tx = threadIdx.x, ty = threadIdx.y;
#pragma unroll
    for(int j=0;j<4;j++) t[ty+j*8][tx] = W[(long)(k0+ty+j*8)*N + n0+tx];
    __syncthreads();
#pragma unroll
    for(int j=0;j<4;j++)
        T[(long)(n0+ty+j*8)*K + k0+tx] = __float2half_rn(t[tx][ty+j*8]);
}

// ---- generic fp16 HMMA GEMM: C[m,n] = sum_k A[m,k]*B[n,k], K-chunk = 64 ----
struct GP {
    const hf *A; long ldA, zA_b, zA_h;
    const hf *B; long ldB, zB_b, zB_h;
    int Kc;                          // number of 64-wide K chunks
    float* Cf; hf* Ch; long ldC, zC_b, zC_h;
    const float *bias, *rbias, *rscale; long rs_z;
    float* part;
    float* attnW;                    // fused normalized fp32 write of A-tiles (attnv)
    int mode;                        // 1 = exp epilogue + row partials
    float scale;
};

template<int NTILE, int MTILE>
__global__ __launch_bounds__(256) void gemm_mma(GP p)
{
    constexpr int WC = (NTILE==128)?4:2, WR = 8/WC;
    constexpr int MW = MTILE/WR, NW = NTILE/WC;  // warp tile
    constexpr int MI = MW/16,  NI = NW/8;
    constexpr int RSTR = 144;                    // 64 halves = 128B + 16B pad
    constexpr int ATILE = MTILE*RSTR;
    constexpr int BTILE = NTILE*RSTR;
    constexpr int STAGE = ATILE + BTILE;
    constexpr int AREP = MTILE/32, BREP = NTILE/32;

    extern __shared__ char smc[];
    float* srow = (float*)smc;                   // 512B: row sums (mode1) / inv cache (attnW)
    const uint32_t smb = s2u(smc);
    const int tid = threadIdx.x, lane = tid&31, w = tid>>5;
    const int wm = w / WC, wn = w % WC;
    const int quad = lane>>2, qi = lane&3;
    const int z = blockIdx.z;
    const long m0 = (long)blockIdx.y*MTILE, n0 = (long)blockIdx.x*NTILE;

    const long zA = (long)(z>>4)*p.zA_b + (long)(z&15)*p.zA_h;
    const long zB = (long)(z>>4)*p.zB_b + (long)(z&15)*p.zB_h;
    const hf *A = p.A + zA, *B = p.B + zB;
    const long zAttn = (long)z*L_*S_;

    if(p.mode==1 && tid < MTILE) srow[tid] = 0.f;
    if(p.attnW && tid < MTILE) srow[tid] = p.rscale[(long)z*p.rs_z + m0 + tid];

    auto load_stage = [&](int t, int buf){
        const uint32_t st = smb + 512 + buf*STAGE;
        const long kp = (long)t*64;
#pragma unroll
        for(int rep=0; rep<AREP; rep++){
            int c = tid + rep*256, row = c>>3, cc = c&7;
            cp16(st + row*RSTR + cc*16, A + (m0+row)*p.ldA + kp + cc*8);
        }
#pragma unroll
        for(int rep=0; rep<BREP; rep++){
            int c = tid + rep*256, row = c>>3, cc = c&7;
            cp16(st + ATILE + row*RSTR + cc*16, B + (n0+row)*p.ldB + kp + cc*8);
        }
        CP_COMMIT();
    };

    float acc[MI][NI][4];
#pragma unroll
    for(int i=0;i<MI;i++)
#pragma unroll
        for(int j=0;j<NI;j++)
#pragma unroll
            for(int e=0;e<4;e++) acc[i][j][e] = 0.f;

    // 2-stage pipeline over 64-wide chunks
    load_stage(0, 0);

    for(int t = 0; t < p.Kc; t++){
        CP_WAIT0();
        __syncthreads();
        if(t+1 < p.Kc) load_stage(t+1, (t+1)&1);

        const int buf = t&1;
        const uint32_t st = smb + 512 + buf*STAGE;
        const uint32_t sB = st + ATILE;

        if(p.attnW){   // fused normalized attn write: each A (P) element passes here once
            const long kp = (long)t*64;
#pragma unroll
            for(int rep=0; rep<AREP; rep++){
                int c = tid + rep*256, row = c>>3, cc = c&7;
                uint4 v = *(uint4*)(smc + 512 + buf*STAGE + row*RSTR + cc*16);
                float iv = srow[row];
                __half2* hp = (__half2*)&v;
                float2 f0=__half22float2(hp[0]), f1=__half22float2(hp[1]);
                float2 f2=__half22float2(hp[2]), f3=__half22float2(hp[3]);
                float* dst = p.attnW + zAttn + (m0+row)*(long)S_ + kp + cc*8;
                *(float4*)dst     = make_float4(f0.x*iv,f0.y*iv,f1.x*iv,f1.y*iv);
                *(float4*)(dst+4) = make_float4(f2.x*iv,f2.y*iv,f3.x*iv,f3.y*iv);
            }
        }

#pragma unroll
        for(int ks=0; ks<4; ks++){
            uint32_t af[MI][4], bfr[NI][2];
            {
                const int j = lane>>3, r = lane&7;
#pragma unroll
                for(int mi=0; mi<MI; mi++){
                    int mrow = wm*MW + mi*16 + (j&1)*8 + r;
                    ldsm4(st + mrow*RSTR + (ks*2 + (j>>1))*16, af[mi]);
                }
            }
            {
                // B via ldmatrix.x4: two adjacent n8 tiles per instruction
                const int g = lane>>3, r = lane&7;
#pragma unroll
                for(int ni=0; ni<NI; ni+=2){
                    int nrow = wn*NW + ni*8 + (g>>1)*8 + r;
                    uint32_t a = sB + nrow*RSTR + (ks*2 + (g&1))*16;
                    uint32_t rr[4]; ldsm4(a, rr);
                    bfr[ni][0]=rr[0];   bfr[ni][1]=rr[1];
                    bfr[ni+1][0]=rr[2]; bfr[ni+1][1]=rr[3];
                }
            }
#pragma unroll
            for(int mi=0; mi<MI; mi++)
#pragma unroll
                for(int ni=0; ni<NI; ni++)
                    mma16816(acc[mi][ni], af[mi], bfr[ni]);
        }
    }

    // epilogue
    const long zc = (long)(z>>4)*p.zC_b + (long)(z&15)*p.zC_h;
#pragma unroll
    for(int mi=0; mi<MI; mi++){
#pragma unroll
        for(int h=0; h<2; h++){
            const int rl = wm*MW + mi*16 + quad + h*8;
            const long row = m0 + rl;
            const float rs = p.rscale ? p.rscale[(long)z*p.rs_z + row] : 1.f;
            const float rb = p.rbias  ? p.rbias[row] : 0.f;
            float rsum = 0.f;
#pragma unroll
            for(int ni=0; ni<NI; ni++){
                const long col = n0 + wn*NW + ni*8 + qi*2;
                float v0 = acc[mi][ni][2*h]   * rs + rb;
                float v1 = acc[mi][ni][2*h+1] * rs + rb;
                if(p.bias){ v0 += p.bias[col]; v1 += p.bias[col+1]; }
                if(p.mode == 1){
                    v0 = exp2f(v0 * p.scale); v1 = exp2f(v1 * p.scale);
                    rsum += v0 + v1;
                }
                const long o = zc + row*p.ldC + col;
                if(p.Cf) *(float2*)(p.Cf + o) = make_float2(v0, v1);
                if(p.Ch) *(uint32_t*)(p.Ch + o) = pkh(v0, v1);
            }
            if(p.mode == 1) atomicAdd(&srow[rl], rsum);
        }
    }
    if(p.mode == 1){
        __syncthreads();
        if(tid < MTILE) p.part[((long)z*L_ + m0 + tid)*32 + blockIdx.x] = srow[tid];
    }
}

// ---- reduce partials -> inv row sums ----
__global__ __launch_bounds__(256) void red_inv(const float* __restrict__ part, float* __restrict__ inv){
    const long row = blockIdx.x*8 + (threadIdx.x>>5);
    const int lane = threadIdx.x&31;
    float v = part[row*32 + lane];
#pragma unroll
    for(int o=16;o;o>>=1) v += __shfl_xor_sync(0xffffffffu, v, o);
    if(lane==0) inv[row] = 1.f/v;
}

// ---- host ----
static inline GP base_gp(){ GP p; memset(&p, 0, sizeof(p)); return p; }

extern "C" void kernel_launch(void* const* d_in, const int* in_sizes, int n_in,
                              void* d_out, int out_size)
{
    const float* latent = (const float*)d_in[0];
    const float* x      = (const float*)d_in[1];
    const float* Wq=(const float*)d_in[2], *bq=(const float*)d_in[3];
    const float* Wc=(const float*)d_in[4], *bc=(const float*)d_in[5];
    const float* Wk=(const float*)d_in[6], *bk=(const float*)d_in[7];
    const float* Wv=(const float*)d_in[8], *bv=(const float*)d_in[9];
    const float* Wo=(const float*)d_in[10],*bo=(const float*)d_in[11];
    float* out  = (float*)d_out;
    float* attn = out + (size_t)B_*L_*LD;

    const int SM128 = 512 + 2*(128*144 + 128*144);  // 74240
    const int SM64  = 512 + 2*(128*144 + 64*144);   // 55808
    const int SM44  = 512 + 2*(64*144 + 64*144);    // 37376
    cudaFuncSetAttribute(gemm_mma<128,128>, cudaFuncAttributeMaxDynamicSharedMemorySize, SM128);
    cudaFuncSetAttribute(gemm_mma<64,128>,  cudaFuncAttributeMaxDynamicSharedMemorySize, SM64);
    cudaFuncSetAttribute(gemm_mma<64,64>,   cudaFuncAttributeMaxDynamicSharedMemorySize, SM44);

    hf *Lx,*Xx,*WqT,*WcT,*WkT,*WvT,*WoT,*Q,*C,*K,*Vt,*P,*AO;
    float *part,*inv;
    cudaGetSymbolAddress((void**)&Lx,g_Lx);   cudaGetSymbolAddress((void**)&Xx,g_Xx);
    cudaGetSymbolAddress((void**)&WqT,g_WqT); cudaGetSymbolAddress((void**)&WcT,g_WcT);
    cudaGetSymbolAddress((void**)&WkT,g_WkT); cudaGetSymbolAddress((void**)&WvT,g_WvT);
    cudaGetSymbolAddress((void**)&WoT,g_WoT);
    cudaGetSymbolAddress((void**)&Q,g_Q);     cudaGetSymbolAddress((void**)&C,g_C);
    cudaGetSymbolAddress((void**)&K,g_K);     cudaGetSymbolAddress((void**)&Vt,g_Vt);
    cudaGetSymbolAddress((void**)&P,g_P);     cudaGetSymbolAddress((void**)&AO,g_AO);
    cudaGetSymbolAddress((void**)&part,g_part); cudaGetSymbolAddress((void**)&inv,g_inv);

    // second stream + fork/join events (created once; capture-legal)
    static cudaStream_t s1 = 0;
    static cudaEvent_t eS = 0, eA = 0, eW = 0, eK = 0, eV = 0;
    if(!s1){
        cudaStreamCreateWithFlags(&s1, cudaStreamNonBlocking);
        cudaEventCreateWithFlags(&eS, cudaEventDisableTiming);
        cudaEventCreateWithFlags(&eA, cudaEventDisableTiming);
        cudaEventCreateWithFlags(&eW, cudaEventDisableTiming);
        cudaEventCreateWithFlags(&eK, cudaEventDisableTiming);
        cudaEventCreateWithFlags(&eV, cudaEventDisableTiming);
    }

    WT5 wt;
    wt.W[0]=Wq; wt.T[0]=WqT; wt.K[0]=LD; wt.N[0]=LD;
    wt.W[1]=Wc; wt.T[1]=WcT; wt.K[1]=ID; wt.N[1]=R_;
    wt.W[2]=Wk; wt.T[2]=WkT; wt.K[2]=R_; wt.N[2]=LD;
    wt.W[3]=Wv; wt.T[3]=WvT; wt.K[3]=R_; wt.N[3]=LD;
    wt.W[4]=Wo; wt.T[4]=WoT; wt.K[4]=LD; wt.N[4]=LD;
    const long nL = (long)B_*L_*LD/4, nX = (long)B_*S_*ID/4;

    GP p;

    // fork s1 off the main stream
    cudaEventRecord(eS, 0);
    cudaStreamWaitEvent(s1, eS, 0);

    // s1: weight converts
    cvtW<<<dim3(32, 64, 5), dim3(32,8), 0, s1>>>(wt);
    cudaEventRecord(eW, s1);
    // s0: activation converts
    cvtA<<<4096, 256>>>(latent, x, Lx, Xx, nL, nL + nX);
    cudaEventRecord(eA, 0);

    // s1: compressed = x @ Wc + bc (needs Xx)
    cudaStreamWaitEvent(s1, eA, 0);
    p = base_gp();
    p.A=Xx; p.ldA=ID; p.B=WcT; p.ldB=ID; p.Kc=ID/64;
    p.Ch=C; p.ldC=R_; p.bias=bc;
    gemm_mma<64,128><<<dim3(R_/64, B_*S_/128, 1), 256, SM64, s1>>>(p);
    // s1: K = comp @ Wk + bk
    p = base_gp();
    p.A=C; p.ldA=R_; p.B=WkT; p.ldB=R_; p.Kc=R_/64;
    p.Ch=K; p.ldC=LD; p.bias=bk;
    gemm_mma<64,128><<<dim3(LD/64, B_*S_/128, 1), 256, SM64, s1>>>(p);
    cudaEventRecord(eK, s1);
    // s1: Vt[b,d,s] = Wv^T[d,:] . comp_b[s,:] + bv[d]  — overlaps scores on s0
    p = base_gp();
    p.A=WvT; p.ldA=R_;
    p.B=C; p.ldB=R_; p.zB_h=(long)S_*R_;
    p.Kc=R_/64; p.Ch=Vt; p.ldC=S_; p.zC_h=(long)LD*S_; p.rbias=bv;
    gemm_mma<64,128><<<dim3(S_/64, LD/128, B_), 256, SM64, s1>>>(p);
    cudaEventRecord(eV, s1);

    // s0: Q = latent @ Wq + bq (needs WqT)
    cudaStreamWaitEvent(0, eW, 0);
    p = base_gp();
    p.A=Lx; p.ldA=LD; p.B=WqT; p.ldB=LD; p.Kc=LD/64;
    p.Ch=Q; p.ldC=LD; p.bias=bq;
    gemm_mma<64,128><<<dim3(LD/64, B_*L_/128, 1), 256, SM64>>>(p);

    // s0: scores (needs K) — Kc=1: single chunk of 64
    cudaStreamWaitEvent(0, eK, 0);
    p = base_gp();
    p.A=Q; p.ldA=LD; p.zA_b=(long)L_*LD; p.zA_h=64;
    p.B=K; p.ldB=LD; p.zB_b=(long)S_*LD; p.zB_h=64;
    p.Kc=1; p.Ch=P; p.ldC=S_; p.zC_b=(long)H_*L_*S_; p.zC_h=(long)L_*S_;
    p.mode=1; p.scale=0.125f*1.44269504088896340736f; p.part=part;
    gemm_mma<128,128><<<dim3(S_/128, L_/128, B_*H_), 256, SM128>>>(p);
    // s0: reduce partials -> 1/rowsum
    red_inv<<<(B_*H_*L_)/8, 256>>>(part, inv);
    // s0: attn_out = (P @ Vt^T) * inv(row); fused normalized fp32 attn write
    cudaStreamWaitEvent(0, eV, 0);
    p = base_gp();
    p.A=P; p.ldA=S_; p.zA_b=(long)H_*L_*S_; p.zA_h=(long)L_*S_;
    p.B=Vt; p.ldB=S_; p.zB_b=(long)LD*S_; p.zB_h=(long)64*S_;
    p.Kc=S_/64; p.Ch=AO; p.ldC=LD; p.zC_b=(long)L_*LD; p.zC_h=64;
    p.rscale=inv; p.rs_z=L_; p.attnW=attn;
    gemm_mma<64,64><<<dim3(1, L_/64, B_*H_), 256, SM44>>>(p);
    // s0: output = AO @ Wo + bo
    p = base_gp();
    p.A=AO; p.ldA=LD; p.B=WoT; p.ldB=LD; p.Kc=LD/64;
    p.Cf=out; p.ldC=LD; p.bias=bo;
    gemm_mma<64,128><<<dim3(LD/64, B_*L_/128, 1), 256, SM64>>>(p);
}